// round 1
// baseline (speedup 1.0000x reference)
#include <cuda_runtime.h>
#include <math.h>

// Problem constants (fixed by reference: B=32768, D=512)
#define BSZ 32768
#define DSZ 512
#define N4  ((BSZ * DSZ) / 4)      // 4,194,304 float4 elements
#define NBLOCKS 1184               // 8 blocks per SM on 148 SMs
#define NTHREADS 256

__device__ float g_weight[BSZ];
__device__ float g_partials[NBLOCKS];

// ---------------------------------------------------------------------------
// Kernel 1: per-row weight
//   inv_freq[j] = sum(attr_num) / attr_num[j]
//   attr_w[b]   = sum_j (attribute[b,j]==1) * inv_freq[j]
//   angle_w[b]  = sum_j (1 - cos(ea[b,j]))
//   weight[b]   = angle_w * attr_w
// ---------------------------------------------------------------------------
__global__ void weight_kernel(const float* __restrict__ ea,
                              const int* __restrict__ attribute,
                              const float* __restrict__ attribute_num) {
    int b = blockIdx.x * blockDim.x + threadIdx.x;
    if (b >= BSZ) return;

    float an[6];
    float s = 0.0f;
#pragma unroll
    for (int j = 0; j < 6; j++) { an[j] = attribute_num[j]; s += an[j]; }

    float attr_w = 0.0f;
#pragma unroll
    for (int j = 0; j < 6; j++) {
        attr_w += (attribute[b * 6 + j] == 1) ? (s / an[j]) : 0.0f;
    }

    float e0 = ea[b * 3 + 0];
    float e1 = ea[b * 3 + 1];
    float e2 = ea[b * 3 + 2];
    float angle_w = 3.0f - cosf(e0) - cosf(e1) - cosf(e2);

    g_weight[b] = angle_w * attr_w;
}

// ---------------------------------------------------------------------------
// Kernel 2: weighted squared-diff partial sums (HBM-bound main loop)
// ---------------------------------------------------------------------------
__global__ void __launch_bounds__(NTHREADS)
mse_partial_kernel(const float4* __restrict__ inp,
                   const float4* __restrict__ lab) {
    float acc = 0.0f;
    const int stride = gridDim.x * blockDim.x;
    for (int i = blockIdx.x * blockDim.x + threadIdx.x; i < N4; i += stride) {
        // 128 float4 per row -> row index = i >> 7. Broadcast-cached.
        float w = g_weight[i >> 7];
        float4 a = inp[i];
        float4 b = lab[i];
        float dx = a.x - b.x;
        float dy = a.y - b.y;
        float dz = a.z - b.z;
        float dw = a.w - b.w;
        acc += w * (dx * dx + dy * dy + dz * dz + dw * dw);
    }

    // Block tree-reduce
    __shared__ float sdata[NTHREADS];
    sdata[threadIdx.x] = acc;
    __syncthreads();
#pragma unroll
    for (int off = NTHREADS / 2; off >= 32; off >>= 1) {
        if (threadIdx.x < off) sdata[threadIdx.x] += sdata[threadIdx.x + off];
        __syncthreads();
    }
    if (threadIdx.x < 32) {
        float v = sdata[threadIdx.x];
#pragma unroll
        for (int off = 16; off > 0; off >>= 1)
            v += __shfl_down_sync(0xFFFFFFFF, v, off);
        if (threadIdx.x == 0) g_partials[blockIdx.x] = v;
    }
}

// ---------------------------------------------------------------------------
// Kernel 3: deterministic final reduce of NBLOCKS partials -> mean
// ---------------------------------------------------------------------------
__global__ void final_reduce_kernel(float* __restrict__ out) {
    __shared__ float sdata[1024];
    float v = 0.0f;
    for (int i = threadIdx.x; i < NBLOCKS; i += 1024) v += g_partials[i];
    sdata[threadIdx.x] = v;
    __syncthreads();
#pragma unroll
    for (int off = 512; off >= 32; off >>= 1) {
        if (threadIdx.x < off) sdata[threadIdx.x] += sdata[threadIdx.x + off];
        __syncthreads();
    }
    if (threadIdx.x < 32) {
        float s = sdata[threadIdx.x];
#pragma unroll
        for (int off = 16; off > 0; off >>= 1)
            s += __shfl_down_sync(0xFFFFFFFF, s, off);
        if (threadIdx.x == 0)
            out[0] = s * (1.0f / (float)(BSZ * DSZ));
    }
}

// ---------------------------------------------------------------------------
// kernel_launch — input order per reference: inp, label, ea, attribute,
// attribute_num, batch_size
// ---------------------------------------------------------------------------
extern "C" void kernel_launch(void* const* d_in, const int* in_sizes, int n_in,
                              void* d_out, int out_size) {
    const float* inp  = (const float*)d_in[0];
    const float* lab  = (const float*)d_in[1];
    const float* ea   = (const float*)d_in[2];
    const int*   attr = (const int*)d_in[3];
    const float* anum = (const float*)d_in[4];
    float* out = (float*)d_out;

    weight_kernel<<<(BSZ + 255) / 256, 256>>>(ea, attr, anum);
    mse_partial_kernel<<<NBLOCKS, NTHREADS>>>((const float4*)inp,
                                              (const float4*)lab);
    final_reduce_kernel<<<1, 1024>>>(out);
}

// round 4
// speedup vs baseline: 1.0749x; 1.0749x over previous
#include <cuda_runtime.h>
#include <math.h>

// Problem constants (fixed by reference: B=32768, D=512)
#define BSZ 32768
#define DSZ 512
#define ROWS_PER_BLOCK 16
#define NBLOCKS (BSZ / ROWS_PER_BLOCK)   // 2048
#define NTHREADS 256
#define F4_PER_ROW (DSZ / 4)             // 128
#define ITERS ((ROWS_PER_BLOCK * F4_PER_ROW) / NTHREADS)  // 8

__device__ float g_partials[NBLOCKS];

// ---------------------------------------------------------------------------
// Main kernel: per-block weight compute (16 rows) fused with the HBM-bound
// weighted squared-diff partial sum. One partial per block.
// ---------------------------------------------------------------------------
__global__ void __launch_bounds__(NTHREADS)
fused_main_kernel(const float4* __restrict__ inp,
                  const float4* __restrict__ lab,
                  const float*  __restrict__ ea,
                  const int*    __restrict__ attribute,
                  const float*  __restrict__ attribute_num) {
    __shared__ float sw[ROWS_PER_BLOCK];
    __shared__ float sdata[NTHREADS];

    const int tid = threadIdx.x;
    const int row0 = blockIdx.x * ROWS_PER_BLOCK;

    // ---- per-row weights for this block's 16 rows (threads 0..15) ----
    if (tid < ROWS_PER_BLOCK) {
        int b = row0 + tid;
        float an[6];
        float s = 0.0f;
#pragma unroll
        for (int j = 0; j < 6; j++) { an[j] = attribute_num[j]; s += an[j]; }
        float attr_w = 0.0f;
#pragma unroll
        for (int j = 0; j < 6; j++) {
            attr_w += (attribute[b * 6 + j] == 1) ? (s / an[j]) : 0.0f;
        }
        float angle_w = 3.0f - cosf(ea[b * 3 + 0])
                             - cosf(ea[b * 3 + 1])
                             - cosf(ea[b * 3 + 2]);
        sw[tid] = angle_w * attr_w;
    }
    __syncthreads();

    // ---- main HBM-bound loop: 8 fully unrolled float4-pair iterations ----
    const int base = row0 * F4_PER_ROW + tid;    // float4 index
    const int wbase = tid >> 7;                  // 0 or 1 (128 float4/row)
    float acc = 0.0f;
#pragma unroll
    for (int k = 0; k < ITERS; k++) {
        int i = base + k * NTHREADS;
        float4 a = __ldcs(&inp[i]);
        float4 b = __ldcs(&lab[i]);
        float w = sw[k * 2 + wbase];             // compile-time smem index
        float dx = a.x - b.x;
        float dy = a.y - b.y;
        float dz = a.z - b.z;
        float dw = a.w - b.w;
        acc += w * (dx * dx + dy * dy + dz * dz + dw * dw);
    }

    // ---- block tree-reduce ----
    sdata[tid] = acc;
    __syncthreads();
#pragma unroll
    for (int off = NTHREADS / 2; off >= 32; off >>= 1) {
        if (tid < off) sdata[tid] += sdata[tid + off];
        __syncthreads();
    }
    if (tid < 32) {
        float v = sdata[tid];
#pragma unroll
        for (int off = 16; off > 0; off >>= 1)
            v += __shfl_down_sync(0xFFFFFFFF, v, off);
        if (tid == 0) g_partials[blockIdx.x] = v;
    }
}

// ---------------------------------------------------------------------------
// Final reduce: deterministic fixed-order sum of 2048 partials -> mean
// ---------------------------------------------------------------------------
__global__ void __launch_bounds__(1024)
final_reduce_kernel(float* __restrict__ out) {
    __shared__ float sdata[1024];
    const int tid = threadIdx.x;
    float v = g_partials[tid] + g_partials[tid + 1024];   // 2048 partials
    sdata[tid] = v;
    __syncthreads();
#pragma unroll
    for (int off = 512; off >= 32; off >>= 1) {
        if (tid < off) sdata[tid] += sdata[tid + off];
        __syncthreads();
    }
    if (tid < 32) {
        float s = sdata[tid];
#pragma unroll
        for (int off = 16; off > 0; off >>= 1)
            s += __shfl_down_sync(0xFFFFFFFF, s, off);
        if (tid == 0)
            out[0] = s * (1.0f / (float)(BSZ * DSZ));
    }
}

// ---------------------------------------------------------------------------
// kernel_launch — input order: inp, label, ea, attribute, attribute_num,
// batch_size
// ---------------------------------------------------------------------------
extern "C" void kernel_launch(void* const* d_in, const int* in_sizes, int n_in,
                              void* d_out, int out_size) {
    const float* inp  = (const float*)d_in[0];
    const float* lab  = (const float*)d_in[1];
    const float* ea   = (const float*)d_in[2];
    const int*   attr = (const int*)d_in[3];
    const float* anum = (const float*)d_in[4];
    float* out = (float*)d_out;

    fused_main_kernel<<<NBLOCKS, NTHREADS>>>((const float4*)inp,
                                             (const float4*)lab,
                                             ea, attr, anum);
    final_reduce_kernel<<<1, 1024>>>(out);
}